// round 8
// baseline (speedup 1.0000x reference)
#include <cuda_runtime.h>

// Problem constants (fixed by the dataset)
#define BB    2
#define NEV   262144          // 2^18 events per batch
#define DBASE 10
#define HH    256
#define WW    256
#define RR    11              // base + 1 references
#define HWSZ  (HH * WW)       // 65536
#define CELLS (BB * 2 * RR * HWSZ)  // 2,883,584 float2 cells (~23 MB per grid)
#define PAD   16              // guard cells (strays only ever poke +-1 cell w/ weight 0)

// Combined scratch buffer, cleared by ONE memset node per launch:
//   A grid  : cells at  [OFF_A + PAD + j]        (even-x0 16B-aligned windows)
//   B grid  : cells at  [OFF_B + 1 + PAD + j]    (odd-x0 16B-aligned windows)
//   partials: BB*RR float2 {loss, inside}
//   counter : one int (block completion count)
#define OFF_A 0
#define OFF_B (CELLS + 2 * PAD)
#define OFF_P (OFF_B + CELLS + 2 * PAD + 2)
#define OFF_C (OFF_P + BB * RR)
#define TOT2  (OFF_C + 1)

__device__ __align__(16) float2 g_buf[TOT2];

#define SPLIT 64
#define NRBLK (BB * RR * SPLIT)

// ---------------------------------------------------------------------------
// Kernel 1: per-event flow sample + bilinear scatter (2x float4 RED per ref)
// ---------------------------------------------------------------------------
__global__ void __launch_bounds__(256)
cm_scatter_kernel(const float* __restrict__ events,
                  const float2* __restrict__ flow) {
    int e = blockIdx.x * blockDim.x + threadIdx.x;
    if (e >= BB * NEV) return;
    int b = e >> 18;  // e / NEV

    // event record = 5 floats; 20B stride -> float4 + float (2 LDGs)
    const float* ev = events + (size_t)e * 5;
    float4 e4 = *reinterpret_cast<const float4*>(ev);  // events buffer is 16B-aligned;
                                                       // 20B stride keeps 4B alignment only,
                                                       // so fall back if misaligned
    float x, y, t, ts, p;
    if (((size_t)ev & 15) == 0) {
        x = e4.x; y = e4.y; t = e4.z; ts = e4.w; p = ev[4];
    } else {
        x = ev[0]; y = ev[1]; t = ev[2]; ts = ev[3]; p = ev[4];
    }

    int pi = min(max((int)p, 0), 1);
    int zi = min(max((int)floorf(t), 0), DBASE - 1);

    // --- bilinear flow sample at (x, y), border-clamped like reference ---
    int sx0 = min(max((int)floorf(x), 0), WW - 2);
    int sy0 = min(max((int)floorf(y), 0), HH - 2);
    float fx = fminf(fmaxf(x - (float)sx0, 0.f), 1.f);
    float fy = fminf(fmaxf(y - (float)sy0, 0.f), 1.f);

    const float2* fm = flow + (((size_t)(b * DBASE + zi) * HH + sy0) * WW + sx0);
    float2 f00 = fm[0];
    float2 f01 = fm[1];
    float2 f10 = fm[WW];
    float2 f11 = fm[WW + 1];

    float w00s = (1.f - fx) * (1.f - fy);
    float w01s = fx * (1.f - fy);
    float w10s = (1.f - fx) * fy;
    float w11s = fx * fy;
    float fu = w00s * f00.x + w01s * f01.x + w10s * f10.x + w11s * f11.x;
    float fv = w00s * f00.y + w01s * f01.y + w10s * f10.y + w11s * f11.y;

    const int chan0 = ((b * 2 + pi) * RR) * HWSZ;
    float2* baseA = g_buf + OFF_A + PAD + chan0;
    float2* baseB = g_buf + OFF_B + 1 + PAD + chan0;

    #pragma unroll
    for (int r = 0; r < RR; r++) {
        float dt = (float)r - t;
        float wx = fmaf(dt, fu, x);
        float wy = fmaf(dt, fv, y);
        float flx = floorf(wx);
        float fly = floorf(wy);
        int x0 = (int)flx;
        int y0 = (int)fly;

        bool vx0 = (unsigned)x0 < (unsigned)WW;
        bool vx1 = (unsigned)(x0 + 1) < (unsigned)WW;
        if (!(vx0 | vx1)) continue;               // whole column pair off-screen

        float ax = wx - flx;
        float ay = wy - fly;
        float wl = vx0 ? (1.f - ax) : 0.f;        // left column weight
        float wr = vx1 ? ax : 0.f;                // right column weight
        float wlt = wl * ts;
        float wrt = wr * ts;

        // pick grid by x0 parity so the 16B window is aligned
        float2* gb = (x0 & 1) ? baseB : baseA;
        int off = r * HWSZ + y0 * WW + x0;

        if ((unsigned)y0 < (unsigned)HH) {
            float s0 = 1.f - ay;
            atomicAdd(reinterpret_cast<float4*>(gb + off),
                      make_float4(wl * s0, wlt * s0, wr * s0, wrt * s0));
        }
        if ((unsigned)(y0 + 1) < (unsigned)HH) {
            atomicAdd(reinterpret_cast<float4*>(gb + off + WW),
                      make_float4(wl * ay, wlt * ay, wr * ay, wrt * ay));
        }
    }
}

// ---------------------------------------------------------------------------
// Kernel 2: partial contrast reduction (read-only) + fused finalize
// ---------------------------------------------------------------------------
__global__ void __launch_bounds__(256)
cm_reduce_kernel(float* __restrict__ out) {
    const int blk = blockIdx.x;
    const int br = blk / SPLIT;                 // 0 .. B*R-1
    const int part = blk % SPLIT;
    const int b = br / RR;
    const int r = br % RR;
    const int tid = threadIdx.x;

    const int chanN = ((b * 2 + 0) * RR + r) * HWSZ;
    const int chanP = ((b * 2 + 1) * RR + r) * HWSZ;
    const float2* An = g_buf + OFF_A + PAD + chanN;
    const float2* Bn = g_buf + OFF_B + 1 + PAD + chanN;
    const float2* Ap = g_buf + OFF_A + PAD + chanP;
    const float2* Bp = g_buf + OFF_B + 1 + PAD + chanP;

    const int per = HWSZ / SPLIT;               // 1024 cells
    const int lo = part * per;

    float loss = 0.f;
    float inside = 0.f;
    // 2 cells per thread-iteration; A read as float4 (16B-aligned at even i)
    for (int i = lo + tid * 2; i < lo + per; i += blockDim.x * 2) {
        float4 a4n = *reinterpret_cast<const float4*>(An + i);
        float4 a4p = *reinterpret_cast<const float4*>(Ap + i);
        float2 bn0 = Bn[i], bn1 = Bn[i + 1];
        float2 bp0 = Bp[i], bp1 = Bp[i + 1];

        float nwe0 = a4n.x + bn0.x, nwt0 = a4n.y + bn0.y;
        float nwe1 = a4n.z + bn1.x, nwt1 = a4n.w + bn1.y;
        float pwe0 = a4p.x + bp0.x, pwt0 = a4p.y + bp0.y;
        float pwe1 = a4p.z + bp1.x, pwt1 = a4p.w + bp1.y;

        float an0 = nwt0 / (nwe0 + 1e-9f);
        float an1 = nwt1 / (nwe1 + 1e-9f);
        float ap0 = pwt0 / (pwe0 + 1e-9f);
        float ap1 = pwt1 / (pwe1 + 1e-9f);
        loss = fmaf(an0, an0, loss);
        loss = fmaf(an1, an1, loss);
        loss = fmaf(ap0, ap0, loss);
        loss = fmaf(ap1, ap1, loss);
        if (nwe0 + pwe0 > 0.f) inside += 1.f;
        if (nwe1 + pwe1 > 0.f) inside += 1.f;
    }

    __shared__ float sl[256];
    __shared__ float si[256];
    sl[tid] = loss;
    si[tid] = inside;
    __syncthreads();
    for (int s = 128; s > 0; s >>= 1) {
        if (tid < s) {
            sl[tid] += sl[tid + s];
            si[tid] += si[tid + s];
        }
        __syncthreads();
    }

    __shared__ int s_last;
    if (tid == 0) {
        float2* partial = g_buf + OFF_P;
        atomicAdd(&partial[br].x, sl[0]);
        atomicAdd(&partial[br].y, si[0]);
        __threadfence();
        int* cnt = reinterpret_cast<int*>(g_buf + OFF_C);
        int done = atomicAdd(cnt, 1);
        s_last = (done == NRBLK - 1) ? 1 : 0;
    }
    __syncthreads();

    if (s_last && tid < BB * RR) {
        float* partial = reinterpret_cast<float*>(g_buf + OFF_P);
        // atomic reads ensure we see other blocks' L2-resident adds
        float lv = atomicAdd(&partial[tid * 2 + 0], 0.f);
        float iv = atomicAdd(&partial[tid * 2 + 1], 0.f);
        out[tid] = lv / (iv + 1e-9f);
    }
}

// ---------------------------------------------------------------------------
extern "C" void kernel_launch(void* const* d_in, const int* in_sizes, int n_in,
                              void* d_out, int out_size) {
    const float*  events = (const float*)d_in[0];
    const float2* flow   = (const float2*)d_in[1];
    float* out = (float*)d_out;

    void* bufp = nullptr;
    cudaGetSymbolAddress(&bufp, g_buf);

    // 1) clear grids + partials + counter in one memset node
    cudaMemsetAsync(bufp, 0, sizeof(float2) * TOT2);

    // 2) scatter all B*N events into all R references
    cm_scatter_kernel<<<(BB * NEV + 255) / 256, 256>>>(events, flow);

    // 3) reduce each (b, r) slice; last block finalizes the 22 outputs
    cm_reduce_kernel<<<NRBLK, 256>>>(out);
}

// round 10
// speedup vs baseline: 1.3825x; 1.3825x over previous
#include <cuda_runtime.h>
#include <cuda_fp16.h>

// Problem constants (fixed by the dataset)
#define BB    2
#define NEV   262144          // 2^18 events per batch
#define DBASE 10
#define HH    256
#define WW    256
#define RR    11              // base + 1 references
#define NCH   (BB * 2 * RR)   // 44 channels = (b, pol, r)

// 2x2-pixel tiled fp16 accumulator.
// Cell = uint4 = 4 x (f16x2) = pixels (dy,dx) in order w[dy*2+dx] = {iwe, iwt}.
// 4 parity grids g = (y0&1)*2 + (x0&1): window origin (x0, y0) maps to ONE cell.
// Tile index tx = x0>>1 (arith shift; x0=-1 -> -1), plane padded by +1 each side.
#define TW    129             // tiles per row incl. pad (tx+1 in [0,128])
#define TPL   (TW * TW)       // 16641 cells per channel plane
#define GRIDSZ ((size_t)NCH * TPL)
#define TOTCELLS (4 * GRIDSZ) // ~2.93M cells * 16 B = ~47 MB

__device__ __align__(16) uint4 g_h[TOTCELLS];
__device__ float g_small[BB * RR * 2 + 2];   // partials {loss, inside} x22 + counter

#define SPLIT 64
#define NRBLK (BB * RR * SPLIT)   // 1408

// ---------------------------------------------------------------------------
// Kernel 1: per-event flow sample + bilinear scatter (ONE v4.f16x2 RED per ref)
// ---------------------------------------------------------------------------
__global__ void __launch_bounds__(256)
cm_scatter_kernel(const float* __restrict__ events,
                  const float2* __restrict__ flow) {
    int e = blockIdx.x * blockDim.x + threadIdx.x;
    if (e >= BB * NEV) return;
    int b = e >> 18;  // e / NEV

    const float* ev = events + (size_t)e * 5;
    float x  = ev[0];
    float y  = ev[1];
    float t  = ev[2];
    float ts = ev[3];
    float p  = ev[4];

    int pi = min(max((int)p, 0), 1);
    int zi = min(max((int)floorf(t), 0), DBASE - 1);

    // --- bilinear flow sample at (x, y), border-clamped like reference ---
    int sx0 = min(max((int)floorf(x), 0), WW - 2);
    int sy0 = min(max((int)floorf(y), 0), HH - 2);
    float fx = fminf(fmaxf(x - (float)sx0, 0.f), 1.f);
    float fy = fminf(fmaxf(y - (float)sy0, 0.f), 1.f);

    const float2* fm = flow + (((size_t)(b * DBASE + zi) * HH + sy0) * WW + sx0);
    float2 f00 = fm[0];
    float2 f01 = fm[1];
    float2 f10 = fm[WW];
    float2 f11 = fm[WW + 1];

    float w00s = (1.f - fx) * (1.f - fy);
    float w01s = fx * (1.f - fy);
    float w10s = (1.f - fx) * fy;
    float w11s = fx * fy;
    float fu = w00s * f00.x + w01s * f01.x + w10s * f10.x + w11s * f11.x;
    float fv = w00s * f00.y + w01s * f01.y + w10s * f10.y + w11s * f11.y;

    const size_t chbase = (size_t)((b * 2 + pi) * RR) * TPL;

    #pragma unroll
    for (int r = 0; r < RR; r++) {
        float dt = (float)r - t;
        float wx = fmaf(dt, fu, x);
        float wy = fmaf(dt, fv, y);
        float flx = floorf(wx);
        float fly = floorf(wy);
        int x0 = (int)flx;
        int y0 = (int)fly;

        // window origin must lie in [-1, 255] on both axes to touch any pixel
        if ((unsigned)(x0 + 1) > 256u) continue;
        if ((unsigned)(y0 + 1) > 256u) continue;

        float ax = wx - flx;
        float ay = wy - fly;
        float wl = (x0 == -1)     ? 0.f : 1.f - ax;   // left column
        float wr = (x0 == WW - 1) ? 0.f : ax;         // right column
        float st = (y0 == -1)     ? 0.f : 1.f - ay;   // top row
        float sb = (y0 == HH - 1) ? 0.f : ay;         // bottom row

        float c00 = wl * st, c01 = wr * st;
        float c10 = wl * sb, c11 = wr * sb;

        __half2 h0 = __floats2half2_rn(c00, c00 * ts);
        __half2 h1 = __floats2half2_rn(c01, c01 * ts);
        __half2 h2 = __floats2half2_rn(c10, c10 * ts);
        __half2 h3 = __floats2half2_rn(c11, c11 * ts);
        unsigned u0 = *reinterpret_cast<unsigned*>(&h0);
        unsigned u1 = *reinterpret_cast<unsigned*>(&h1);
        unsigned u2 = *reinterpret_cast<unsigned*>(&h2);
        unsigned u3 = *reinterpret_cast<unsigned*>(&h3);

        int g = ((y0 & 1) << 1) | (x0 & 1);
        uint4* cell = g_h + (size_t)g * GRIDSZ + chbase + (size_t)r * TPL
                    + (size_t)((y0 >> 1) + 1) * TW + ((x0 >> 1) + 1);

        asm volatile("red.global.add.noftz.v4.f16x2 [%0], {%1, %2, %3, %4};"
                     :: "l"(cell), "r"(u0), "r"(u1), "r"(u2), "r"(u3)
                     : "memory");
    }
}

// ---------------------------------------------------------------------------
// Kernel 2: gather-reduce (one thread per 2x2 pixel block) + fused finalize
// ---------------------------------------------------------------------------
__device__ __forceinline__ const uint4* cellp(int g, int ch, int ty, int tx) {
    return g_h + (size_t)g * GRIDSZ + (size_t)ch * TPL + (size_t)(ty + 1) * TW + (tx + 1);
}

__device__ __forceinline__ void acch(float2& a, unsigned w) {
    __half2 h = *reinterpret_cast<__half2*>(&w);
    float2 f = __half22float2(h);
    a.x += f.x;
    a.y += f.y;
}

// gather the 4 pixel accumulators of aligned 2x2 block (i, j) for channel ch
__device__ __forceinline__ void gather_block(int ch, int i, int j,
                                             float2& p00, float2& p10,
                                             float2& p01, float2& p11) {
    uint4 A   = __ldg(cellp(0, ch, j,     i));
    uint4 B0  = __ldg(cellp(1, ch, j,     i - 1));
    uint4 B1  = __ldg(cellp(1, ch, j,     i));
    uint4 C0  = __ldg(cellp(2, ch, j - 1, i));
    uint4 C1  = __ldg(cellp(2, ch, j,     i));
    uint4 D00 = __ldg(cellp(3, ch, j - 1, i - 1));
    uint4 D01 = __ldg(cellp(3, ch, j - 1, i));
    uint4 D10 = __ldg(cellp(3, ch, j,     i - 1));
    uint4 D11 = __ldg(cellp(3, ch, j,     i));

    p00 = make_float2(0.f, 0.f); p10 = make_float2(0.f, 0.f);
    p01 = make_float2(0.f, 0.f); p11 = make_float2(0.f, 0.f);
    // pixel (2i,   2j)  : g0 w0, g1 w1 (tile i-1), g2 w2 (tile j-1), g3 w3
    acch(p00, A.x);  acch(p00, B0.y);  acch(p00, C0.z);  acch(p00, D00.w);
    // pixel (2i+1, 2j)  : g0 w1, g1 w0, g2 w3, g3 w2
    acch(p10, A.y);  acch(p10, B1.x);  acch(p10, C0.w);  acch(p10, D01.z);
    // pixel (2i,   2j+1): g0 w2, g1 w3, g2 w0, g3 w1
    acch(p01, A.z);  acch(p01, B0.w);  acch(p01, C1.x);  acch(p01, D10.y);
    // pixel (2i+1, 2j+1): g0 w3, g1 w2, g2 w1, g3 w0
    acch(p11, A.w);  acch(p11, B1.z);  acch(p11, C1.y);  acch(p11, D11.x);
}

__global__ void __launch_bounds__(256)
cm_reduce_kernel(float* __restrict__ out) {
    const int blk = blockIdx.x;
    const int br = blk / SPLIT;                 // 0 .. B*R-1
    const int part = blk % SPLIT;
    const int b = br / RR;
    const int r = br % RR;
    const int tid = threadIdx.x;

    const int chN = (b * 2 + 0) * RR + r;
    const int chP = (b * 2 + 1) * RR + r;

    // this thread's aligned 2x2 pixel block
    const int idx = part * 256 + tid;           // 0 .. 16383
    const int j = idx >> 7;                     // tile row  0..127
    const int i = idx & 127;                    // tile col  0..127

    float2 n00, n10, n01, n11;
    gather_block(chN, i, j, n00, n10, n01, n11);
    float2 q00, q10, q01, q11;
    gather_block(chP, i, j, q00, q10, q01, q11);

    float a;
    float loss = 0.f;
    a = n00.y / (n00.x + 1e-9f); loss = fmaf(a, a, loss);
    a = n10.y / (n10.x + 1e-9f); loss = fmaf(a, a, loss);
    a = n01.y / (n01.x + 1e-9f); loss = fmaf(a, a, loss);
    a = n11.y / (n11.x + 1e-9f); loss = fmaf(a, a, loss);
    a = q00.y / (q00.x + 1e-9f); loss = fmaf(a, a, loss);
    a = q10.y / (q10.x + 1e-9f); loss = fmaf(a, a, loss);
    a = q01.y / (q01.x + 1e-9f); loss = fmaf(a, a, loss);
    a = q11.y / (q11.x + 1e-9f); loss = fmaf(a, a, loss);

    float inside = 0.f;
    if (n00.x + q00.x > 0.f) inside += 1.f;
    if (n10.x + q10.x > 0.f) inside += 1.f;
    if (n01.x + q01.x > 0.f) inside += 1.f;
    if (n11.x + q11.x > 0.f) inside += 1.f;

    __shared__ float sl[256];
    __shared__ float si[256];
    sl[tid] = loss;
    si[tid] = inside;
    __syncthreads();
    for (int s = 128; s > 0; s >>= 1) {
        if (tid < s) {
            sl[tid] += sl[tid + s];
            si[tid] += si[tid + s];
        }
        __syncthreads();
    }

    __shared__ int s_last;
    if (tid == 0) {
        atomicAdd(&g_small[br * 2 + 0], sl[0]);
        atomicAdd(&g_small[br * 2 + 1], si[0]);
        __threadfence();
        int* cnt = reinterpret_cast<int*>(&g_small[BB * RR * 2]);
        int done = atomicAdd(cnt, 1);
        s_last = (done == NRBLK - 1) ? 1 : 0;
    }
    __syncthreads();

    if (s_last && tid < BB * RR) {
        // atomic reads ensure we see other blocks' L2-resident adds
        float lv = atomicAdd(&g_small[tid * 2 + 0], 0.f);
        float iv = atomicAdd(&g_small[tid * 2 + 1], 0.f);
        out[tid] = lv / (iv + 1e-9f);
    }
}

// ---------------------------------------------------------------------------
extern "C" void kernel_launch(void* const* d_in, const int* in_sizes, int n_in,
                              void* d_out, int out_size) {
    const float*  events = (const float*)d_in[0];
    const float2* flow   = (const float2*)d_in[1];
    float* out = (float*)d_out;

    void* hp = nullptr;
    cudaGetSymbolAddress(&hp, g_h);
    void* sp = nullptr;
    cudaGetSymbolAddress(&sp, g_small);

    // 1) clear accumulator grids + partials + counter
    cudaMemsetAsync(hp, 0, sizeof(uint4) * TOTCELLS);
    cudaMemsetAsync(sp, 0, sizeof(float) * (BB * RR * 2 + 2));

    // 2) scatter all B*N events into all R references (one RED per event-ref)
    cm_scatter_kernel<<<(BB * NEV + 255) / 256, 256>>>(events, flow);

    // 3) gather-reduce each (b, r) slice; last block finalizes the 22 outputs
    cm_reduce_kernel<<<NRBLK, 256>>>(out);
}

// round 11
// speedup vs baseline: 1.5152x; 1.0960x over previous
#include <cuda_runtime.h>
#include <cuda_fp16.h>

// Problem constants (fixed by the dataset)
#define BB    2
#define NEV   262144          // 2^18 events per batch
#define DBASE 10
#define HH    256
#define WW    256
#define RR    11              // base + 1 references
#define NCH   (BB * 2 * RR)   // 44 channels = (b, pol, r)

// 2x2-pixel tiled fp16 accumulator.
// Cell = uint4 = 4 x (f16x2) = pixels (dy,dx) in order w[dy*2+dx] = {iwe, iwt}.
// 4 parity grids g = (y0&1)*2 + (x0&1): window origin (x0, y0) maps to ONE cell.
// Tile index tx = x0>>1 (arith shift; x0=-1 -> -1), plane padded by +1 each side.
#define TW    129             // tiles per row incl. pad (tx+1 in [0,128])
#define TPL   (TW * TW)       // 16641 cells per channel plane
#define GRIDSZ ((size_t)NCH * TPL)
#define TOTCELLS (4 * GRIDSZ) // ~2.93M cells * 16 B = ~47 MB

__device__ __align__(16) uint4 g_h[TOTCELLS];
__device__ float g_small[BB * RR * 2 + 2];   // partials {loss, inside} x22 + counter
                                             // zero-initialized; reduce kernel resets it

#define SPLIT 32
#define NRBLK (BB * RR * SPLIT)   // 704  (single wave, 2 items/thread)

// ---------------------------------------------------------------------------
// Kernel 1: per-event flow sample + bilinear scatter (ONE v4.f16x2 RED per ref)
// ---------------------------------------------------------------------------
__global__ void __launch_bounds__(256)
cm_scatter_kernel(const float* __restrict__ events,
                  const float2* __restrict__ flow) {
    int e = blockIdx.x * blockDim.x + threadIdx.x;
    if (e >= BB * NEV) return;
    int b = e >> 18;  // e / NEV

    const float* ev = events + (size_t)e * 5;
    float x  = ev[0];
    float y  = ev[1];
    float t  = ev[2];
    float ts = ev[3];
    float p  = ev[4];

    int pi = min(max((int)p, 0), 1);
    int zi = min(max((int)floorf(t), 0), DBASE - 1);

    // --- bilinear flow sample at (x, y), border-clamped like reference ---
    int sx0 = min(max((int)floorf(x), 0), WW - 2);
    int sy0 = min(max((int)floorf(y), 0), HH - 2);
    float fx = fminf(fmaxf(x - (float)sx0, 0.f), 1.f);
    float fy = fminf(fmaxf(y - (float)sy0, 0.f), 1.f);

    const float2* fm = flow + (((size_t)(b * DBASE + zi) * HH + sy0) * WW + sx0);
    float2 f00 = fm[0];
    float2 f01 = fm[1];
    float2 f10 = fm[WW];
    float2 f11 = fm[WW + 1];

    float w00s = (1.f - fx) * (1.f - fy);
    float w01s = fx * (1.f - fy);
    float w10s = (1.f - fx) * fy;
    float w11s = fx * fy;
    float fu = w00s * f00.x + w01s * f01.x + w10s * f10.x + w11s * f11.x;
    float fv = w00s * f00.y + w01s * f01.y + w10s * f10.y + w11s * f11.y;

    const size_t chbase = (size_t)((b * 2 + pi) * RR) * TPL;

    #pragma unroll
    for (int r = 0; r < RR; r++) {
        float dt = (float)r - t;
        float wx = fmaf(dt, fu, x);
        float wy = fmaf(dt, fv, y);
        float flx = floorf(wx);
        float fly = floorf(wy);
        int x0 = (int)flx;
        int y0 = (int)fly;

        // window origin must lie in [-1, 255] on both axes to touch any pixel
        if ((unsigned)(x0 + 1) > 256u) continue;
        if ((unsigned)(y0 + 1) > 256u) continue;

        float ax = wx - flx;
        float ay = wy - fly;
        float wl = (x0 == -1)     ? 0.f : 1.f - ax;   // left column
        float wr = (x0 == WW - 1) ? 0.f : ax;         // right column
        float st = (y0 == -1)     ? 0.f : 1.f - ay;   // top row
        float sb = (y0 == HH - 1) ? 0.f : ay;         // bottom row

        float c00 = wl * st, c01 = wr * st;
        float c10 = wl * sb, c11 = wr * sb;

        __half2 h0 = __floats2half2_rn(c00, c00 * ts);
        __half2 h1 = __floats2half2_rn(c01, c01 * ts);
        __half2 h2 = __floats2half2_rn(c10, c10 * ts);
        __half2 h3 = __floats2half2_rn(c11, c11 * ts);
        unsigned u0 = *reinterpret_cast<unsigned*>(&h0);
        unsigned u1 = *reinterpret_cast<unsigned*>(&h1);
        unsigned u2 = *reinterpret_cast<unsigned*>(&h2);
        unsigned u3 = *reinterpret_cast<unsigned*>(&h3);

        int g = ((y0 & 1) << 1) | (x0 & 1);
        uint4* cell = g_h + (size_t)g * GRIDSZ + chbase + (size_t)r * TPL
                    + (size_t)((y0 >> 1) + 1) * TW + ((x0 >> 1) + 1);

        asm volatile("red.global.add.noftz.v4.f16x2 [%0], {%1, %2, %3, %4};"
                     :: "l"(cell), "r"(u0), "r"(u1), "r"(u2), "r"(u3)
                     : "memory");
    }
}

// ---------------------------------------------------------------------------
// Kernel 2: gather-reduce (2 tile-blocks per thread) + fused finalize + reset
// ---------------------------------------------------------------------------
__device__ __forceinline__ const uint4* cellp(int g, int ch, int ty, int tx) {
    return g_h + (size_t)g * GRIDSZ + (size_t)ch * TPL + (size_t)(ty + 1) * TW + (tx + 1);
}

__device__ __forceinline__ void acch(float2& a, unsigned w) {
    __half2 h = *reinterpret_cast<__half2*>(&w);
    float2 f = __half22float2(h);
    a.x += f.x;
    a.y += f.y;
}

// gather the 4 pixel accumulators of aligned 2x2 block (i, j) for channel ch
__device__ __forceinline__ void gather_block(int ch, int i, int j,
                                             float2& p00, float2& p10,
                                             float2& p01, float2& p11) {
    uint4 A   = __ldg(cellp(0, ch, j,     i));
    uint4 B0  = __ldg(cellp(1, ch, j,     i - 1));
    uint4 B1  = __ldg(cellp(1, ch, j,     i));
    uint4 C0  = __ldg(cellp(2, ch, j - 1, i));
    uint4 C1  = __ldg(cellp(2, ch, j,     i));
    uint4 D00 = __ldg(cellp(3, ch, j - 1, i - 1));
    uint4 D01 = __ldg(cellp(3, ch, j - 1, i));
    uint4 D10 = __ldg(cellp(3, ch, j,     i - 1));
    uint4 D11 = __ldg(cellp(3, ch, j,     i));

    p00 = make_float2(0.f, 0.f); p10 = make_float2(0.f, 0.f);
    p01 = make_float2(0.f, 0.f); p11 = make_float2(0.f, 0.f);
    acch(p00, A.x);  acch(p00, B0.y);  acch(p00, C0.z);  acch(p00, D00.w);
    acch(p10, A.y);  acch(p10, B1.x);  acch(p10, C0.w);  acch(p10, D01.z);
    acch(p01, A.z);  acch(p01, B0.w);  acch(p01, C1.x);  acch(p01, D10.y);
    acch(p11, A.w);  acch(p11, B1.z);  acch(p11, C1.y);  acch(p11, D11.x);
}

__device__ __forceinline__ void item_accum(int chN, int chP, int item,
                                           float& loss, float& inside) {
    const int j = item >> 7;                    // tile row  0..127
    const int i = item & 127;                   // tile col  0..127

    float2 n00, n10, n01, n11;
    gather_block(chN, i, j, n00, n10, n01, n11);
    float2 q00, q10, q01, q11;
    gather_block(chP, i, j, q00, q10, q01, q11);

    float a;
    a = n00.y / (n00.x + 1e-9f); loss = fmaf(a, a, loss);
    a = n10.y / (n10.x + 1e-9f); loss = fmaf(a, a, loss);
    a = n01.y / (n01.x + 1e-9f); loss = fmaf(a, a, loss);
    a = n11.y / (n11.x + 1e-9f); loss = fmaf(a, a, loss);
    a = q00.y / (q00.x + 1e-9f); loss = fmaf(a, a, loss);
    a = q10.y / (q10.x + 1e-9f); loss = fmaf(a, a, loss);
    a = q01.y / (q01.x + 1e-9f); loss = fmaf(a, a, loss);
    a = q11.y / (q11.x + 1e-9f); loss = fmaf(a, a, loss);

    if (n00.x + q00.x > 0.f) inside += 1.f;
    if (n10.x + q10.x > 0.f) inside += 1.f;
    if (n01.x + q01.x > 0.f) inside += 1.f;
    if (n11.x + q11.x > 0.f) inside += 1.f;
}

__global__ void __launch_bounds__(256)
cm_reduce_kernel(float* __restrict__ out) {
    const int blk = blockIdx.x;
    const int br = blk / SPLIT;                 // 0 .. B*R-1
    const int part = blk % SPLIT;
    const int b = br / RR;
    const int r = br % RR;
    const int tid = threadIdx.x;

    const int chN = (b * 2 + 0) * RR + r;
    const int chP = (b * 2 + 1) * RR + r;

    // this block covers 512 tile-blocks; each thread takes 2 (tid, tid+256)
    const int base = part * 512;                // of 16384 per channel pair

    float loss = 0.f;
    float inside = 0.f;
    item_accum(chN, chP, base + tid,       loss, inside);
    item_accum(chN, chP, base + tid + 256, loss, inside);

    __shared__ float sl[256];
    __shared__ float si[256];
    sl[tid] = loss;
    si[tid] = inside;
    __syncthreads();
    for (int s = 128; s > 0; s >>= 1) {
        if (tid < s) {
            sl[tid] += sl[tid + s];
            si[tid] += si[tid + s];
        }
        __syncthreads();
    }

    __shared__ int s_last;
    if (tid == 0) {
        atomicAdd(&g_small[br * 2 + 0], sl[0]);
        atomicAdd(&g_small[br * 2 + 1], si[0]);
        __threadfence();
        int* cnt = reinterpret_cast<int*>(&g_small[BB * RR * 2]);
        int done = atomicAdd(cnt, 1);
        s_last = (done == NRBLK - 1) ? 1 : 0;
    }
    __syncthreads();

    if (s_last) {
        if (tid < BB * RR) {
            // atomic reads ensure we see other blocks' L2-resident adds
            float lv = atomicAdd(&g_small[tid * 2 + 0], 0.f);
            float iv = atomicAdd(&g_small[tid * 2 + 1], 0.f);
            out[tid] = lv / (iv + 1e-9f);
            // reset partials for the next replay
            g_small[tid * 2 + 0] = 0.f;
            g_small[tid * 2 + 1] = 0.f;
        }
        if (tid == 0) {
            __threadfence();
            *reinterpret_cast<int*>(&g_small[BB * RR * 2]) = 0;  // reset counter
        }
    }
}

// ---------------------------------------------------------------------------
extern "C" void kernel_launch(void* const* d_in, const int* in_sizes, int n_in,
                              void* d_out, int out_size) {
    const float*  events = (const float*)d_in[0];
    const float2* flow   = (const float2*)d_in[1];
    float* out = (float*)d_out;

    void* hp = nullptr;
    cudaGetSymbolAddress(&hp, g_h);

    // 1) clear accumulator grids (partials/counter self-reset in reduce)
    cudaMemsetAsync(hp, 0, sizeof(uint4) * TOTCELLS);

    // 2) scatter all B*N events into all R references (one RED per event-ref)
    cm_scatter_kernel<<<(BB * NEV + 255) / 256, 256>>>(events, flow);

    // 3) gather-reduce each (b, r) slice; last block finalizes the 22 outputs
    cm_reduce_kernel<<<NRBLK, 256>>>(out);
}